// round 15
// baseline (speedup 1.0000x reference)
#include <cuda_runtime.h>
#include <cuda_fp16.h>
#include <math_constants.h>
#include <cstdint>

// ---------------- problem constants ----------------
#define BATCH 8
#define SEQ   2048
#define EMB   1024
#define HEAD  1024
#define MTOT  (BATCH * SEQ)
#define NQKV  (3 * HEAD)

// ---------------- mma.sync GEMM tiling ----------------
#define BM 128
#define BN 256
#define BK 64
#define NTHREADS 256
// SMEM row stride: 64 + 8 pad fp16 = 144 bytes (9*16B -> conflict-free ldmatrix)
#define ROWB 144
#define A_BYTES (128 * ROWB)            // 18432
#define B_BYTES (256 * ROWB)            // 36864
#define OFF_A 0
#define OFF_B (A_BYTES)
#define SMEM_DYN (128 * 257 * 4)        // 131584 epilogue fp32 buf; operands (55296) overlap

// ---------------- static scratch (fp16) ----------------
__device__ __half g_X[(size_t)MTOT * EMB];
__device__ __half g_W[(size_t)NQKV * EMB];
__device__ __half g_Q[(size_t)MTOT * HEAD];
__device__ __half g_K[(size_t)MTOT * HEAD];
__device__ __half g_VT[(size_t)BATCH * HEAD * SEQ];   // [b][h][t]
__device__ float  g_S[(size_t)BATCH * SEQ * SEQ];
__device__ __half g_P[(size_t)BATCH * SEQ * SEQ];

// ---------------- helpers ----------------
__device__ __forceinline__ uint32_t smem_u32(const void* p) {
    uint32_t a;
    asm("{ .reg .u64 t; cvta.to.shared.u64 t, %1; cvt.u32.u64 %0, t; }" : "=r"(a) : "l"(p));
    return a;
}
#define CP_ASYNC16(dst, src) \
    asm volatile("cp.async.cg.shared.global [%0], [%1], 16;" :: "r"(dst), "l"(src))
#define CP_COMMIT() asm volatile("cp.async.commit_group;")
#define CP_WAIT0()  asm volatile("cp.async.wait_group 0;")

__device__ __forceinline__ void ldsm_x4(uint32_t& r0, uint32_t& r1, uint32_t& r2, uint32_t& r3,
                                        uint32_t addr) {
    asm volatile("ldmatrix.sync.aligned.m8n8.x4.shared.b16 {%0,%1,%2,%3}, [%4];"
                 : "=r"(r0), "=r"(r1), "=r"(r2), "=r"(r3) : "r"(addr));
}
__device__ __forceinline__ void mma_f16(float* c, const uint32_t* a, uint32_t b0, uint32_t b1) {
    asm volatile("mma.sync.aligned.m16n8k16.row.col.f32.f16.f16.f32 "
                 "{%0,%1,%2,%3}, {%4,%5,%6,%7}, {%8,%9}, {%0,%1,%2,%3};"
                 : "+f"(c[0]), "+f"(c[1]), "+f"(c[2]), "+f"(c[3])
                 : "r"(a[0]), "r"(a[1]), "r"(a[2]), "r"(a[3]), "r"(b0), "r"(b1));
}

// ---------------------------------------------------------------------------
// convert: fp32 -> fp16.  which: 0 = x, 1..3 = Wq/Wk/Wv into stacked W
// ---------------------------------------------------------------------------
__global__ __launch_bounds__(256) void convert_kernel(const float* __restrict__ src,
                                                      int which, int n4)
{
    int i = blockIdx.x * 256 + threadIdx.x;
    if (i >= n4) return;
    __half* dst = (which == 0) ? g_X : g_W + (size_t)(which - 1) * HEAD * EMB;
    float4 v = ((const float4*)src)[i];
    ushort4 u;
    u.x = __half_as_ushort(__float2half(v.x));
    u.y = __half_as_ushort(__float2half(v.y));
    u.z = __half_as_ushort(__float2half(v.z));
    u.w = __half_as_ushort(__float2half(v.w));
    ((ushort4*)dst)[i] = u;
}

// ---------------------------------------------------------------------------
// mma.sync fp16 single-pass GEMM, 128x256x64 CTA tile, 8 warps of 64x64.
// Single-buffered cp.async (R14 skeleton, BN doubled for L2-traffic reuse).
// MODE 0: [16384,3072] = X * Wstack^T  -> Q, K, V^T (fp16)
// MODE 1: S[b] = scale * Q K^T         (tile-level causal skip, 2*bx<=by live)
// MODE 2: O[b] = P * VT^T              (k-loop truncated at row tile ceiling)
// ---------------------------------------------------------------------------
template <int MODE>
__global__ __launch_bounds__(NTHREADS) void gemm_mma(float* __restrict__ outp)
{
    const int bx = blockIdx.x, by = blockIdx.y, bz = blockIdx.z;
    if (MODE == 1 && 2 * bx > by) return;      // tile fully above diagonal

    const int rowBase = by * BM;
    const int colBase = bx * BN;

    const __half *A, *B;
    int lda, ldb, kChunks;
    if (MODE == 0) {
        A = g_X; B = g_W;
        lda = EMB; ldb = EMB; kChunks = EMB / BK;
    } else if (MODE == 1) {
        size_t o = (size_t)bz * SEQ * HEAD;
        A = g_Q + o; B = g_K + o;
        lda = HEAD; ldb = HEAD; kChunks = HEAD / BK;
    } else {
        A = g_P + (size_t)bz * SEQ * SEQ;
        B = g_VT + (size_t)bz * HEAD * SEQ;
        lda = SEQ; ldb = SEQ; kChunks = (rowBase + BM) / BK;
    }

    extern __shared__ char sm[];
    const uint32_t sbase = smem_u32(sm);

    const int tid  = threadIdx.x;
    const int lane = tid & 31;
    const int wid  = tid >> 5;
    const int wm   = wid >> 2;      // 0..1 (row 64-block)
    const int wn   = wid & 3;       // 0..3 (col 64-block)

    const __half* gA = A + (size_t)rowBase * lda;
    const __half* gB = B + (size_t)colBase * ldb;

    // ---- ldmatrix addresses ----
    const int aRow = wm * 64 + (lane & 15);                      // + mt*16
    const int aCol = (lane >> 4) * 8;
    const int bRow = wn * 64 + (lane & 7) + ((lane >> 4) << 3);  // + g*16
    const int bCol = ((lane >> 3) & 1) * 8;

    float acc[4][8][4];
#pragma unroll
    for (int mt = 0; mt < 4; mt++)
#pragma unroll
        for (int nt = 0; nt < 8; nt++)
#pragma unroll
            for (int i = 0; i < 4; i++) acc[mt][nt][i] = 0.f;

    // ------------------- K loop (single-buffered, BK=64) -------------------
    for (int ck = 0; ck < kChunks; ck++) {
        const int k0 = ck * BK;
        // A: 128 rows x 8 segs = 1024 segs (4/thread)
#pragma unroll
        for (int i = 0; i < 4; i++) {
            const int t   = i * NTHREADS + tid;
            const int r   = t >> 3;
            const int seg = t & 7;
            CP_ASYNC16(sbase + OFF_A + r * ROWB + seg * 16,
                       gA + (size_t)r * lda + k0 + seg * 8);
        }
        // B: 256 rows x 8 segs = 2048 segs (8/thread)
#pragma unroll
        for (int i = 0; i < 8; i++) {
            const int t   = i * NTHREADS + tid;
            const int r   = t >> 3;
            const int seg = t & 7;
            CP_ASYNC16(sbase + OFF_B + r * ROWB + seg * 16,
                       gB + (size_t)r * ldb + k0 + seg * 8);
        }
        CP_COMMIT();
        CP_WAIT0();
        __syncthreads();

#pragma unroll
        for (int ks = 0; ks < 4; ks++) {
            const int kc = ks * 16;
            uint32_t a[4][4], b[4][4];
#pragma unroll
            for (int mt = 0; mt < 4; mt++) {
                const uint32_t ad = sbase + OFF_A +
                                    (aRow + mt * 16) * ROWB + (kc + aCol) * 2;
                ldsm_x4(a[mt][0], a[mt][1], a[mt][2], a[mt][3], ad);
            }
#pragma unroll
            for (int g = 0; g < 4; g++) {
                const uint32_t bd = sbase + OFF_B +
                                    (bRow + g * 16) * ROWB + (kc + bCol) * 2;
                ldsm_x4(b[g][0], b[g][1], b[g][2], b[g][3], bd);
            }
#pragma unroll
            for (int mt = 0; mt < 4; mt++)
#pragma unroll
                for (int nt = 0; nt < 8; nt++)
                    mma_f16(acc[mt][nt], a[mt], b[nt >> 1][(nt & 1) * 2],
                            b[nt >> 1][(nt & 1) * 2 + 1]);
        }
        __syncthreads();    // tile consumed; next chunk may overwrite
    }

    // ------------------- epilogue: stage to padded SMEM fp32 -------------------
    float* buf = (float*)sm;
    {
        const int rq = lane >> 2;
        const int cq = (lane & 3) * 2;
#pragma unroll
        for (int mt = 0; mt < 4; mt++)
#pragma unroll
            for (int nt = 0; nt < 8; nt++) {
                const int r = wm * 64 + mt * 16 + rq;
                const int c = wn * 64 + nt * 8 + cq;
                buf[r * 257 + c]           = acc[mt][nt][0];
                buf[r * 257 + c + 1]       = acc[mt][nt][1];
                buf[(r + 8) * 257 + c]     = acc[mt][nt][2];
                buf[(r + 8) * 257 + c + 1] = acc[mt][nt][3];
            }
    }
    __syncthreads();

    if (MODE == 0 && colBase >= 2 * HEAD) {
        // V segment -> transposed fp16: g_VT[b][h][t]; lanes sweep t (coalesced)
#pragma unroll 4
        for (int it = 0; it < 128; it++) {
            const int idx = it * NTHREADS + tid;
            const int hcol = idx >> 7, trow = idx & 127;
            const float v = buf[trow * 257 + hcol];
            const int m = rowBase + trow;
            const int b = m >> 11, tt = m & 2047;
            const int h = colBase - 2 * HEAD + hcol;
            g_VT[((size_t)b * HEAD + h) * SEQ + tt] = __float2half(v);
        }
    } else {
#pragma unroll 4
        for (int it = 0; it < 128; it++) {
            const int idx = it * NTHREADS + tid;
            const int row = idx >> 8, col = idx & 255;
            const float v = buf[row * 257 + col];
            const int m = rowBase + row;
            const int n = colBase + col;
            if (MODE == 0) {
                if (n < HEAD) g_Q[(size_t)m * HEAD + n] = __float2half(v);
                else          g_K[(size_t)m * HEAD + (n - HEAD)] = __float2half(v);
            } else if (MODE == 1) {
                g_S[((size_t)bz * SEQ + m) * SEQ + n] = v * 0.03125f;
            } else {
                outp[((size_t)bz * SEQ + m) * HEAD + n] = v;
            }
        }
    }
}

// ---------------------------------------------------------------------------
// causal softmax on g_S rows; single-exp (stash e in g_S, normalize on
// read-back). Writes P fp16, zero-fill to 128-ceiling.
// ---------------------------------------------------------------------------
__global__ __launch_bounds__(256) void softmax_kernel()
{
    const int t = blockIdx.x;
    const int b = blockIdx.y;
    const size_t off = ((size_t)b * SEQ + t) * SEQ;
    float* __restrict__ row = g_S + off;
    const int L = t + 1;

    const int tid = threadIdx.x;
    const int lane = tid & 31;
    const int wid = tid >> 5;
    __shared__ float red[32];

    float lmax = -CUDART_INF_F;
    for (int i = tid; i < L; i += 256) lmax = fmaxf(lmax, row[i]);
#pragma unroll
    for (int o = 16; o > 0; o >>= 1) lmax = fmaxf(lmax, __shfl_xor_sync(0xffffffffu, lmax, o));
    if (lane == 0) red[wid] = lmax;
    __syncthreads();
    if (tid < 32) {
        float v = (tid < 8) ? red[tid] : -CUDART_INF_F;
#pragma unroll
        for (int o = 4; o > 0; o >>= 1) v = fmaxf(v, __shfl_xor_sync(0xffffffffu, v, o));
        if (tid == 0) red[0] = v;
    }
    __syncthreads();
    const float m = red[0];
    __syncthreads();

    float lsum = 0.f;
    for (int i = tid; i < L; i += 256) {
        const float e = __expf(row[i] - m);
        row[i] = e;
        lsum += e;
    }
#pragma unroll
    for (int o = 16; o > 0; o >>= 1) lsum += __shfl_xor_sync(0xffffffffu, lsum, o);
    if (lane == 0) red[wid] = lsum;
    __syncthreads();
    if (tid < 32) {
        float v = (tid < 8) ? red[tid] : 0.f;
#pragma unroll
        for (int o = 4; o > 0; o >>= 1) v += __shfl_xor_sync(0xffffffffu, v, o);
        if (tid == 0) red[0] = v;
    }
    __syncthreads();
    const float inv = 1.f / red[0];

    for (int i = tid; i < L; i += 256) g_P[off + i] = __float2half(row[i] * inv);
    const int kCeil = ((t >> 7) + 1) << 7;     // PV reads only up to this tile edge
    const __half z = __float2half(0.f);
    for (int i = L + tid; i < kCeil; i += 256) g_P[off + i] = z;
}

// ---------------------------------------------------------------------------
extern "C" void kernel_launch(void* const* d_in, const int* in_sizes, int n_in,
                              void* d_out, int out_size)
{
    const float* x  = (const float*)d_in[0];
    const float* Wq = (const float*)d_in[1];
    const float* Wk = (const float*)d_in[2];
    const float* Wv = (const float*)d_in[3];
    float* out = (float*)d_out;

    cudaFuncSetAttribute(gemm_mma<0>, cudaFuncAttributeMaxDynamicSharedMemorySize, SMEM_DYN);
    cudaFuncSetAttribute(gemm_mma<1>, cudaFuncAttributeMaxDynamicSharedMemorySize, SMEM_DYN);
    cudaFuncSetAttribute(gemm_mma<2>, cudaFuncAttributeMaxDynamicSharedMemorySize, SMEM_DYN);

    // 1. fp32 -> fp16 conversions
    const int nx4 = MTOT * EMB / 4;
    convert_kernel<<<(nx4 + 255) / 256, 256>>>(x, 0, nx4);
    const int nw4 = HEAD * EMB / 4;
    convert_kernel<<<(nw4 + 255) / 256, 256>>>(Wq, 1, nw4);
    convert_kernel<<<(nw4 + 255) / 256, 256>>>(Wk, 2, nw4);
    convert_kernel<<<(nw4 + 255) / 256, 256>>>(Wv, 3, nw4);

    // 2. QKV projection (tensor cores)
    dim3 g1(NQKV / BN, MTOT / BM);
    gemm_mma<0><<<g1, NTHREADS, SMEM_DYN>>>(nullptr);

    // 3. S = scale * Q K^T (causal tile skip)
    dim3 g2(SEQ / BN, SEQ / BM, BATCH);
    gemm_mma<1><<<g2, NTHREADS, SMEM_DYN>>>(nullptr);

    // 4. softmax -> P fp16 (single exp)
    dim3 g3(SEQ, BATCH);
    softmax_kernel<<<g3, 256>>>();

    // 5. O = P V
    dim3 g4(HEAD / BN, SEQ / BM, BATCH);
    gemm_mma<2><<<g4, NTHREADS, SMEM_DYN>>>(out);
}

// round 16
// speedup vs baseline: 1.3274x; 1.3274x over previous
#include <cuda_runtime.h>
#include <cuda_fp16.h>
#include <math_constants.h>
#include <cstdint>

// ---------------- problem constants ----------------
#define BATCH 8
#define SEQ   2048
#define EMB   1024
#define HEAD  1024
#define MTOT  (BATCH * SEQ)
#define NQKV  (3 * HEAD)

// ---------------- mma.sync GEMM tiling ----------------
#define BM 128
#define BN 128
#define BK 128
#define NTHREADS 256
// SMEM row stride: 128 + 8 pad fp16 = 272 bytes (17*16B -> conflict-free ldmatrix)
#define ROWB 272
#define ARR_BYTES (128 * ROWB)          // 34816 per operand array (A, B)
#define SMEM_DYN (2 * ARR_BYTES)        // 69632; epilogue fp32 buf (66048) overlaps

// ---------------- static scratch (fp16) ----------------
__device__ __half g_X[(size_t)MTOT * EMB];
__device__ __half g_W[(size_t)NQKV * EMB];
__device__ __half g_Q[(size_t)MTOT * HEAD];
__device__ __half g_K[(size_t)MTOT * HEAD];
__device__ __half g_VT[(size_t)BATCH * HEAD * SEQ];   // [b][h][t]
__device__ float  g_S[(size_t)BATCH * SEQ * SEQ];
__device__ __half g_P[(size_t)BATCH * SEQ * SEQ];

// ---------------- helpers ----------------
__device__ __forceinline__ uint32_t smem_u32(const void* p) {
    uint32_t a;
    asm("{ .reg .u64 t; cvta.to.shared.u64 t, %1; cvt.u32.u64 %0, t; }" : "=r"(a) : "l"(p));
    return a;
}
#define CP_ASYNC16(dst, src) \
    asm volatile("cp.async.cg.shared.global [%0], [%1], 16;" :: "r"(dst), "l"(src))
#define CP_COMMIT() asm volatile("cp.async.commit_group;")
#define CP_WAIT0()  asm volatile("cp.async.wait_group 0;")

__device__ __forceinline__ void ldsm_x4(uint32_t& r0, uint32_t& r1, uint32_t& r2, uint32_t& r3,
                                        uint32_t addr) {
    asm volatile("ldmatrix.sync.aligned.m8n8.x4.shared.b16 {%0,%1,%2,%3}, [%4];"
                 : "=r"(r0), "=r"(r1), "=r"(r2), "=r"(r3) : "r"(addr));
}
__device__ __forceinline__ void mma_f16(float* c, const uint32_t* a, uint32_t b0, uint32_t b1) {
    asm volatile("mma.sync.aligned.m16n8k16.row.col.f32.f16.f16.f32 "
                 "{%0,%1,%2,%3}, {%4,%5,%6,%7}, {%8,%9}, {%0,%1,%2,%3};"
                 : "+f"(c[0]), "+f"(c[1]), "+f"(c[2]), "+f"(c[3])
                 : "r"(a[0]), "r"(a[1]), "r"(a[2]), "r"(a[3]), "r"(b0), "r"(b1));
}

// ---------------------------------------------------------------------------
// convert: fp32 -> fp16.  which: 0 = x, 1..3 = Wq/Wk/Wv into stacked W
// ---------------------------------------------------------------------------
__global__ __launch_bounds__(256) void convert_kernel(const float* __restrict__ src,
                                                      int which, int n4)
{
    int i = blockIdx.x * 256 + threadIdx.x;
    if (i >= n4) return;
    __half* dst = (which == 0) ? g_X : g_W + (size_t)(which - 1) * HEAD * EMB;
    float4 v = ((const float4*)src)[i];
    ushort4 u;
    u.x = __half_as_ushort(__float2half(v.x));
    u.y = __half_as_ushort(__float2half(v.y));
    u.z = __half_as_ushort(__float2half(v.z));
    u.w = __half_as_ushort(__float2half(v.w));
    ((ushort4*)dst)[i] = u;
}

// ---------------------------------------------------------------------------
// mma.sync fp16 single-pass GEMM, 128x128x128 tile, NT, 256 threads (8 warps,
// 64x32 warp tiles). Single-buffered cp.async (R14 skeleton, BK doubled —
// chunk bytes now equal the proven bf16-BK64 sweet spot).
// MODE 0: [16384,3072] = X * Wstack^T  -> Q, K, V^T (fp16)
// MODE 1: S[b] = scale * Q K^T         (tile-level causal skip)
// MODE 2: O[b] = P * VT^T              (k-loop truncated at row tile ceiling)
// ---------------------------------------------------------------------------
template <int MODE>
__global__ __launch_bounds__(NTHREADS) void gemm_mma(float* __restrict__ outp)
{
    const int bx = blockIdx.x, by = blockIdx.y, bz = blockIdx.z;
    if (MODE == 1 && bx > by) return;          // tile fully above diagonal

    const int rowBase = by * BM;
    const int colBase = bx * BN;

    const __half *A, *B;
    int lda, ldb, kChunks;
    if (MODE == 0) {
        A = g_X; B = g_W;
        lda = EMB; ldb = EMB; kChunks = EMB / BK;
    } else if (MODE == 1) {
        size_t o = (size_t)bz * SEQ * HEAD;
        A = g_Q + o; B = g_K + o;
        lda = HEAD; ldb = HEAD; kChunks = HEAD / BK;
    } else {
        A = g_P + (size_t)bz * SEQ * SEQ;
        B = g_VT + (size_t)bz * HEAD * SEQ;
        lda = SEQ; ldb = SEQ; kChunks = (rowBase + BM) / BK;
    }

    extern __shared__ char sm[];
    const uint32_t sbase = smem_u32(sm);

    const int tid  = threadIdx.x;
    const int lane = tid & 31;
    const int wid  = tid >> 5;
    const int wm   = wid >> 2;      // 0..1
    const int wn   = wid & 3;       // 0..3

    const __half* gA = A + (size_t)rowBase * lda;
    const __half* gB = B + (size_t)colBase * ldb;

    // ---- ldmatrix addresses ----
    const int aRow = wm * 64 + (lane & 15);
    const int aCol = (lane >> 4) * 8;
    const int bRow = wn * 32 + (lane & 7) + ((lane >> 4) << 3);
    const int bCol = ((lane >> 3) & 1) * 8;

    float acc[4][4][4];
#pragma unroll
    for (int mt = 0; mt < 4; mt++)
#pragma unroll
        for (int nt = 0; nt < 4; nt++)
#pragma unroll
            for (int i = 0; i < 4; i++) acc[mt][nt][i] = 0.f;

    // ------------------- K loop (single-buffered, BK=128) -------------------
    for (int ck = 0; ck < kChunks; ck++) {
        const int k0 = ck * BK;
        // A: 128 rows x 16 segs = 2048 segs (8/thread); B same
#pragma unroll
        for (int i = 0; i < 8; i++) {
            const int t   = i * NTHREADS + tid;
            const int r   = t >> 4;
            const int seg = t & 15;
            CP_ASYNC16(sbase + 0 * ARR_BYTES + r * ROWB + seg * 16,
                       gA + (size_t)r * lda + k0 + seg * 8);
        }
#pragma unroll
        for (int i = 0; i < 8; i++) {
            const int t   = i * NTHREADS + tid;
            const int r   = t >> 4;
            const int seg = t & 15;
            CP_ASYNC16(sbase + 1 * ARR_BYTES + r * ROWB + seg * 16,
                       gB + (size_t)r * ldb + k0 + seg * 8);
        }
        CP_COMMIT();
        CP_WAIT0();
        __syncthreads();

#pragma unroll
        for (int ks = 0; ks < 8; ks++) {
            const int kc = ks * 16;
            uint32_t a[4][4], b[2][4];
#pragma unroll
            for (int mt = 0; mt < 4; mt++) {
                const uint32_t ad = sbase + 0 * ARR_BYTES +
                                    (aRow + mt * 16) * ROWB + (kc + aCol) * 2;
                ldsm_x4(a[mt][0], a[mt][1], a[mt][2], a[mt][3], ad);
            }
#pragma unroll
            for (int g = 0; g < 2; g++) {
                const uint32_t bd = sbase + 1 * ARR_BYTES +
                                    (bRow + g * 16) * ROWB + (kc + bCol) * 2;
                ldsm_x4(b[g][0], b[g][1], b[g][2], b[g][3], bd);
            }
#pragma unroll
            for (int mt = 0; mt < 4; mt++)
#pragma unroll
                for (int nt = 0; nt < 4; nt++)
                    mma_f16(acc[mt][nt], a[mt], b[nt >> 1][(nt & 1) * 2],
                            b[nt >> 1][(nt & 1) * 2 + 1]);
        }
        __syncthreads();    // tile consumed; next chunk may overwrite
    }

    // ------------------- epilogue: stage to padded SMEM fp32 -------------------
    float* buf = (float*)sm;
    {
        const int rq = lane >> 2;
        const int cq = (lane & 3) * 2;
#pragma unroll
        for (int mt = 0; mt < 4; mt++)
#pragma unroll
            for (int nt = 0; nt < 4; nt++) {
                const int r = wm * 64 + mt * 16 + rq;
                const int c = wn * 32 + nt * 8 + cq;
                buf[r * 129 + c]           = acc[mt][nt][0];
                buf[r * 129 + c + 1]       = acc[mt][nt][1];
                buf[(r + 8) * 129 + c]     = acc[mt][nt][2];
                buf[(r + 8) * 129 + c + 1] = acc[mt][nt][3];
            }
    }
    __syncthreads();

    if (MODE == 0 && colBase >= 2 * HEAD) {
        // V segment -> transposed fp16: g_VT[b][h][t]; lanes sweep t (coalesced)
#pragma unroll 4
        for (int it = 0; it < 64; it++) {
            const int idx = it * NTHREADS + tid;
            const int hcol = idx >> 7, trow = idx & 127;
            const float v = buf[trow * 129 + hcol];
            const int m = rowBase + trow;
            const int b = m >> 11, tt = m & 2047;
            const int h = colBase - 2 * HEAD + hcol;
            g_VT[((size_t)b * HEAD + h) * SEQ + tt] = __float2half(v);
        }
    } else {
#pragma unroll 4
        for (int it = 0; it < 64; it++) {
            const int idx = it * NTHREADS + tid;
            const int row = idx >> 7, col = idx & 127;
            const float v = buf[row * 129 + col];
            const int m = rowBase + row;
            const int n = colBase + col;
            if (MODE == 0) {
                if (n < HEAD) g_Q[(size_t)m * HEAD + n] = __float2half(v);
                else          g_K[(size_t)m * HEAD + (n - HEAD)] = __float2half(v);
            } else if (MODE == 1) {
                g_S[((size_t)bz * SEQ + m) * SEQ + n] = v * 0.03125f;
            } else {
                outp[((size_t)bz * SEQ + m) * HEAD + n] = v;
            }
        }
    }
}

// ---------------------------------------------------------------------------
// causal softmax on g_S rows; single-exp (stash e in g_S, normalize on
// read-back). Writes P fp16, zero-fill to 128-ceiling.
// ---------------------------------------------------------------------------
__global__ __launch_bounds__(256) void softmax_kernel()
{
    const int t = blockIdx.x;
    const int b = blockIdx.y;
    const size_t off = ((size_t)b * SEQ + t) * SEQ;
    float* __restrict__ row = g_S + off;
    const int L = t + 1;

    const int tid = threadIdx.x;
    const int lane = tid & 31;
    const int wid = tid >> 5;
    __shared__ float red[32];

    float lmax = -CUDART_INF_F;
    for (int i = tid; i < L; i += 256) lmax = fmaxf(lmax, row[i]);
#pragma unroll
    for (int o = 16; o > 0; o >>= 1) lmax = fmaxf(lmax, __shfl_xor_sync(0xffffffffu, lmax, o));
    if (lane == 0) red[wid] = lmax;
    __syncthreads();
    if (tid < 32) {
        float v = (tid < 8) ? red[tid] : -CUDART_INF_F;
#pragma unroll
        for (int o = 4; o > 0; o >>= 1) v = fmaxf(v, __shfl_xor_sync(0xffffffffu, v, o));
        if (tid == 0) red[0] = v;
    }
    __syncthreads();
    const float m = red[0];
    __syncthreads();

    float lsum = 0.f;
    for (int i = tid; i < L; i += 256) {
        const float e = __expf(row[i] - m);
        row[i] = e;
        lsum += e;
    }
#pragma unroll
    for (int o = 16; o > 0; o >>= 1) lsum += __shfl_xor_sync(0xffffffffu, lsum, o);
    if (lane == 0) red[wid] = lsum;
    __syncthreads();
    if (tid < 32) {
        float v = (tid < 8) ? red[tid] : 0.f;
#pragma unroll
        for (int o = 4; o > 0; o >>= 1) v += __shfl_xor_sync(0xffffffffu, v, o);
        if (tid == 0) red[0] = v;
    }
    __syncthreads();
    const float inv = 1.f / red[0];

    for (int i = tid; i < L; i += 256) g_P[off + i] = __float2half(row[i] * inv);
    const int kCeil = ((t >> 7) + 1) << 7;     // PV reads only up to this tile edge
    const __half z = __float2half(0.f);
    for (int i = L + tid; i < kCeil; i += 256) g_P[off + i] = z;
}

// ---------------------------------------------------------------------------
extern "C" void kernel_launch(void* const* d_in, const int* in_sizes, int n_in,
                              void* d_out, int out_size)
{
    const float* x  = (const float*)d_in[0];
    const float* Wq = (const float*)d_in[1];
    const float* Wk = (const float*)d_in[2];
    const float* Wv = (const float*)d_in[3];
    float* out = (float*)d_out;

    cudaFuncSetAttribute(gemm_mma<0>, cudaFuncAttributeMaxDynamicSharedMemorySize, SMEM_DYN);
    cudaFuncSetAttribute(gemm_mma<1>, cudaFuncAttributeMaxDynamicSharedMemorySize, SMEM_DYN);
    cudaFuncSetAttribute(gemm_mma<2>, cudaFuncAttributeMaxDynamicSharedMemorySize, SMEM_DYN);

    // 1. fp32 -> fp16 conversions
    const int nx4 = MTOT * EMB / 4;
    convert_kernel<<<(nx4 + 255) / 256, 256>>>(x, 0, nx4);
    const int nw4 = HEAD * EMB / 4;
    convert_kernel<<<(nw4 + 255) / 256, 256>>>(Wq, 1, nw4);
    convert_kernel<<<(nw4 + 255) / 256, 256>>>(Wk, 2, nw4);
    convert_kernel<<<(nw4 + 255) / 256, 256>>>(Wv, 3, nw4);

    // 2. QKV projection (tensor cores)
    dim3 g1(NQKV / BN, MTOT / BM);
    gemm_mma<0><<<g1, NTHREADS, SMEM_DYN>>>(nullptr);

    // 3. S = scale * Q K^T (causal tile skip)
    dim3 g2(SEQ / BN, SEQ / BM, BATCH);
    gemm_mma<1><<<g2, NTHREADS, SMEM_DYN>>>(nullptr);

    // 4. softmax -> P fp16 (single exp)
    dim3 g3(SEQ, BATCH);
    softmax_kernel<<<g3, 256>>>();

    // 5. O = P V
    dim3 g4(HEAD / BN, SEQ / BM, BATCH);
    gemm_mma<2><<<g4, NTHREADS, SMEM_DYN>>>(out);
}

// round 17
// speedup vs baseline: 1.3277x; 1.0002x over previous
#include <cuda_runtime.h>
#include <cuda_fp16.h>
#include <math_constants.h>
#include <cstdint>

// ---------------- problem constants ----------------
#define BATCH 8
#define SEQ   2048
#define EMB   1024
#define HEAD  1024
#define MTOT  (BATCH * SEQ)
#define NQKV  (3 * HEAD)

// ---------------- mma.sync GEMM tiling ----------------
#define BM 128
#define BN 128
#define BK 128
#define NTHREADS 256
// SMEM row stride: 128 + 8 pad fp16 = 272 bytes (17*16B -> conflict-free ldmatrix)
#define ROWB 272
#define ARR_BYTES (128 * ROWB)          // 34816 per operand array (A, B)
#define SMEM_DYN (2 * ARR_BYTES)        // 69632; epilogue fp32 buf (66048) overlaps

// ---------------- static scratch (fp16) ----------------
__device__ __half g_X[(size_t)MTOT * EMB];
__device__ __half g_W[(size_t)NQKV * EMB];
__device__ __half g_Q[(size_t)MTOT * HEAD];
__device__ __half g_K[(size_t)MTOT * HEAD];
__device__ __half g_VT[(size_t)BATCH * HEAD * SEQ];   // [b][h][t]
__device__ float  g_S[(size_t)BATCH * SEQ * SEQ];
__device__ __half g_P[(size_t)BATCH * SEQ * SEQ];     // UNNORMALIZED exp(s - max)
__device__ float  g_invsum[(size_t)MTOT];             // per (b,t) row: 1/sum(e)

// ---------------- helpers ----------------
__device__ __forceinline__ uint32_t smem_u32(const void* p) {
    uint32_t a;
    asm("{ .reg .u64 t; cvta.to.shared.u64 t, %1; cvt.u32.u64 %0, t; }" : "=r"(a) : "l"(p));
    return a;
}
#define CP_ASYNC16(dst, src) \
    asm volatile("cp.async.cg.shared.global [%0], [%1], 16;" :: "r"(dst), "l"(src))
#define CP_COMMIT() asm volatile("cp.async.commit_group;")
#define CP_WAIT0()  asm volatile("cp.async.wait_group 0;")

__device__ __forceinline__ void ldsm_x4(uint32_t& r0, uint32_t& r1, uint32_t& r2, uint32_t& r3,
                                        uint32_t addr) {
    asm volatile("ldmatrix.sync.aligned.m8n8.x4.shared.b16 {%0,%1,%2,%3}, [%4];"
                 : "=r"(r0), "=r"(r1), "=r"(r2), "=r"(r3) : "r"(addr));
}
__device__ __forceinline__ void mma_f16(float* c, const uint32_t* a, uint32_t b0, uint32_t b1) {
    asm volatile("mma.sync.aligned.m16n8k16.row.col.f32.f16.f16.f32 "
                 "{%0,%1,%2,%3}, {%4,%5,%6,%7}, {%8,%9}, {%0,%1,%2,%3};"
                 : "+f"(c[0]), "+f"(c[1]), "+f"(c[2]), "+f"(c[3])
                 : "r"(a[0]), "r"(a[1]), "r"(a[2]), "r"(a[3]), "r"(b0), "r"(b1));
}

// ---------------------------------------------------------------------------
// convert: fp32 -> fp16.  which: 0 = x, 1..3 = Wq/Wk/Wv into stacked W
// ---------------------------------------------------------------------------
__global__ __launch_bounds__(256) void convert_kernel(const float* __restrict__ src,
                                                      int which, int n4)
{
    int i = blockIdx.x * 256 + threadIdx.x;
    if (i >= n4) return;
    __half* dst = (which == 0) ? g_X : g_W + (size_t)(which - 1) * HEAD * EMB;
    float4 v = ((const float4*)src)[i];
    ushort4 u;
    u.x = __half_as_ushort(__float2half(v.x));
    u.y = __half_as_ushort(__float2half(v.y));
    u.z = __half_as_ushort(__float2half(v.z));
    u.w = __half_as_ushort(__float2half(v.w));
    ((ushort4*)dst)[i] = u;
}

// ---------------------------------------------------------------------------
// mma.sync fp16 single-pass GEMM, 128x128x128 tile, NT (R16 structure).
// MODE 0: [16384,3072] = X * Wstack^T  -> Q, K, V^T (fp16)
// MODE 1: S[b] = scale * Q K^T         (tile-level causal skip)
// MODE 2: O[b] = (P_unnorm * VT^T) * invsum[m]   (k-loop truncated causally)
// ---------------------------------------------------------------------------
template <int MODE>
__global__ __launch_bounds__(NTHREADS) void gemm_mma(float* __restrict__ outp)
{
    const int bx = blockIdx.x, by = blockIdx.y, bz = blockIdx.z;
    if (MODE == 1 && bx > by) return;          // tile fully above diagonal

    const int rowBase = by * BM;
    const int colBase = bx * BN;

    const __half *A, *B;
    int lda, ldb, kChunks;
    if (MODE == 0) {
        A = g_X; B = g_W;
        lda = EMB; ldb = EMB; kChunks = EMB / BK;
    } else if (MODE == 1) {
        size_t o = (size_t)bz * SEQ * HEAD;
        A = g_Q + o; B = g_K + o;
        lda = HEAD; ldb = HEAD; kChunks = HEAD / BK;
    } else {
        A = g_P + (size_t)bz * SEQ * SEQ;
        B = g_VT + (size_t)bz * HEAD * SEQ;
        lda = SEQ; ldb = SEQ; kChunks = (rowBase + BM) / BK;
    }

    extern __shared__ char sm[];
    const uint32_t sbase = smem_u32(sm);

    const int tid  = threadIdx.x;
    const int lane = tid & 31;
    const int wid  = tid >> 5;
    const int wm   = wid >> 2;      // 0..1
    const int wn   = wid & 3;       // 0..3

    const __half* gA = A + (size_t)rowBase * lda;
    const __half* gB = B + (size_t)colBase * ldb;

    // ---- ldmatrix addresses ----
    const int aRow = wm * 64 + (lane & 15);
    const int aCol = (lane >> 4) * 8;
    const int bRow = wn * 32 + (lane & 7) + ((lane >> 4) << 3);
    const int bCol = ((lane >> 3) & 1) * 8;

    float acc[4][4][4];
#pragma unroll
    for (int mt = 0; mt < 4; mt++)
#pragma unroll
        for (int nt = 0; nt < 4; nt++)
#pragma unroll
            for (int i = 0; i < 4; i++) acc[mt][nt][i] = 0.f;

    // ------------------- K loop (single-buffered, BK=128) -------------------
    for (int ck = 0; ck < kChunks; ck++) {
        const int k0 = ck * BK;
#pragma unroll
        for (int i = 0; i < 8; i++) {
            const int t   = i * NTHREADS + tid;
            const int r   = t >> 4;
            const int seg = t & 15;
            CP_ASYNC16(sbase + 0 * ARR_BYTES + r * ROWB + seg * 16,
                       gA + (size_t)r * lda + k0 + seg * 8);
        }
#pragma unroll
        for (int i = 0; i < 8; i++) {
            const int t   = i * NTHREADS + tid;
            const int r   = t >> 4;
            const int seg = t & 15;
            CP_ASYNC16(sbase + 1 * ARR_BYTES + r * ROWB + seg * 16,
                       gB + (size_t)r * ldb + k0 + seg * 8);
        }
        CP_COMMIT();
        CP_WAIT0();
        __syncthreads();

#pragma unroll
        for (int ks = 0; ks < 8; ks++) {
            const int kc = ks * 16;
            uint32_t a[4][4], b[2][4];
#pragma unroll
            for (int mt = 0; mt < 4; mt++) {
                const uint32_t ad = sbase + 0 * ARR_BYTES +
                                    (aRow + mt * 16) * ROWB + (kc + aCol) * 2;
                ldsm_x4(a[mt][0], a[mt][1], a[mt][2], a[mt][3], ad);
            }
#pragma unroll
            for (int g = 0; g < 2; g++) {
                const uint32_t bd = sbase + 1 * ARR_BYTES +
                                    (bRow + g * 16) * ROWB + (kc + bCol) * 2;
                ldsm_x4(b[g][0], b[g][1], b[g][2], b[g][3], bd);
            }
#pragma unroll
            for (int mt = 0; mt < 4; mt++)
#pragma unroll
                for (int nt = 0; nt < 4; nt++)
                    mma_f16(acc[mt][nt], a[mt], b[nt >> 1][(nt & 1) * 2],
                            b[nt >> 1][(nt & 1) * 2 + 1]);
        }
        __syncthreads();    // tile consumed; next chunk may overwrite
    }

    // ------------------- epilogue: stage to padded SMEM fp32 -------------------
    float* buf = (float*)sm;
    {
        const int rq = lane >> 2;
        const int cq = (lane & 3) * 2;
#pragma unroll
        for (int mt = 0; mt < 4; mt++)
#pragma unroll
            for (int nt = 0; nt < 4; nt++) {
                const int r = wm * 64 + mt * 16 + rq;
                const int c = wn * 32 + nt * 8 + cq;
                buf[r * 129 + c]           = acc[mt][nt][0];
                buf[r * 129 + c + 1]       = acc[mt][nt][1];
                buf[(r + 8) * 129 + c]     = acc[mt][nt][2];
                buf[(r + 8) * 129 + c + 1] = acc[mt][nt][3];
            }
    }
    __syncthreads();

    if (MODE == 0 && colBase >= 2 * HEAD) {
        // V segment -> transposed fp16: g_VT[b][h][t]; lanes sweep t (coalesced)
#pragma unroll 4
        for (int it = 0; it < 64; it++) {
            const int idx = it * NTHREADS + tid;
            const int hcol = idx >> 7, trow = idx & 127;
            const float v = buf[trow * 129 + hcol];
            const int m = rowBase + trow;
            const int b = m >> 11, tt = m & 2047;
            const int h = colBase - 2 * HEAD + hcol;
            g_VT[((size_t)b * HEAD + h) * SEQ + tt] = __float2half(v);
        }
    } else {
#pragma unroll 4
        for (int it = 0; it < 64; it++) {
            const int idx = it * NTHREADS + tid;
            const int row = idx >> 7, col = idx & 127;
            const float v = buf[row * 129 + col];
            const int m = rowBase + row;
            const int n = colBase + col;
            if (MODE == 0) {
                if (n < HEAD) g_Q[(size_t)m * HEAD + n] = __float2half(v);
                else          g_K[(size_t)m * HEAD + (n - HEAD)] = __float2half(v);
            } else if (MODE == 1) {
                g_S[((size_t)bz * SEQ + m) * SEQ + n] = v * 0.03125f;
            } else {
                // deferred softmax normalization
                outp[((size_t)bz * SEQ + m) * HEAD + n] =
                    v * g_invsum[(size_t)bz * SEQ + m];
            }
        }
    }
}

// ---------------------------------------------------------------------------
// causal softmax (deferred normalization): pass 1 max, pass 2 exp -> write
// UNNORMALIZED e to g_P (fp16) + row inv_sum to g_invsum. No third pass.
// Zero-fill g_P to the 128-ceiling.
// ---------------------------------------------------------------------------
__global__ __launch_bounds__(256) void softmax_kernel()
{
    const int t = blockIdx.x;
    const int b = blockIdx.y;
    const size_t off = ((size_t)b * SEQ + t) * SEQ;
    const float* __restrict__ row = g_S + off;
    const int L = t + 1;

    const int tid = threadIdx.x;
    const int lane = tid & 31;
    const int wid = tid >> 5;
    __shared__ float red[32];

    float lmax = -CUDART_INF_F;
    for (int i = tid; i < L; i += 256) lmax = fmaxf(lmax, row[i]);
#pragma unroll
    for (int o = 16; o > 0; o >>= 1) lmax = fmaxf(lmax, __shfl_xor_sync(0xffffffffu, lmax, o));
    if (lane == 0) red[wid] = lmax;
    __syncthreads();
    if (tid < 32) {
        float v = (tid < 8) ? red[tid] : -CUDART_INF_F;
#pragma unroll
        for (int o = 4; o > 0; o >>= 1) v = fmaxf(v, __shfl_xor_sync(0xffffffffu, v, o));
        if (tid == 0) red[0] = v;
    }
    __syncthreads();
    const float m = red[0];
    __syncthreads();

    // exp once; write unnormalized e (fp16) to g_P
    float lsum = 0.f;
    for (int i = tid; i < L; i += 256) {
        const float e = __expf(row[i] - m);
        g_P[off + i] = __float2half(e);
        lsum += e;
    }
#pragma unroll
    for (int o = 16; o > 0; o >>= 1) lsum += __shfl_xor_sync(0xffffffffu, lsum, o);
    if (lane == 0) red[wid] = lsum;
    __syncthreads();
    if (tid < 32) {
        float v = (tid < 8) ? red[tid] : 0.f;
#pragma unroll
        for (int o = 4; o > 0; o >>= 1) v += __shfl_xor_sync(0xffffffffu, v, o);
        if (tid == 0) g_invsum[(size_t)b * SEQ + t] = 1.f / v;
    }

    const int kCeil = ((t >> 7) + 1) << 7;     // PV reads only up to this tile edge
    const __half z = __float2half(0.f);
    for (int i = L + tid; i < kCeil; i += 256) g_P[off + i] = z;
}

// ---------------------------------------------------------------------------
extern "C" void kernel_launch(void* const* d_in, const int* in_sizes, int n_in,
                              void* d_out, int out_size)
{
    const float* x  = (const float*)d_in[0];
    const float* Wq = (const float*)d_in[1];
    const float* Wk = (const float*)d_in[2];
    const float* Wv = (const float*)d_in[3];
    float* out = (float*)d_out;

    cudaFuncSetAttribute(gemm_mma<0>, cudaFuncAttributeMaxDynamicSharedMemorySize, SMEM_DYN);
    cudaFuncSetAttribute(gemm_mma<1>, cudaFuncAttributeMaxDynamicSharedMemorySize, SMEM_DYN);
    cudaFuncSetAttribute(gemm_mma<2>, cudaFuncAttributeMaxDynamicSharedMemorySize, SMEM_DYN);

    // 1. fp32 -> fp16 conversions
    const int nx4 = MTOT * EMB / 4;
    convert_kernel<<<(nx4 + 255) / 256, 256>>>(x, 0, nx4);
    const int nw4 = HEAD * EMB / 4;
    convert_kernel<<<(nw4 + 255) / 256, 256>>>(Wq, 1, nw4);
    convert_kernel<<<(nw4 + 255) / 256, 256>>>(Wk, 2, nw4);
    convert_kernel<<<(nw4 + 255) / 256, 256>>>(Wv, 3, nw4);

    // 2. QKV projection (tensor cores)
    dim3 g1(NQKV / BN, MTOT / BM);
    gemm_mma<0><<<g1, NTHREADS, SMEM_DYN>>>(nullptr);

    // 3. S = scale * Q K^T (causal tile skip)
    dim3 g2(SEQ / BN, SEQ / BM, BATCH);
    gemm_mma<1><<<g2, NTHREADS, SMEM_DYN>>>(nullptr);

    // 4. softmax -> unnormalized e (fp16) + invsum
    dim3 g3(SEQ, BATCH);
    softmax_kernel<<<g3, 256>>>();

    // 5. O = (P V) * invsum
    dim3 g4(HEAD / BN, SEQ / BM, BATCH);
    gemm_mma<2><<<g4, NTHREADS, SMEM_DYN>>>(out);
}